// round 14
// baseline (speedup 1.0000x reference)
#include <cuda_runtime.h>
#include <cstdint>
#include <math.h>

#define SEQ 512
#define BATCH 128
#define INDIM 256
#define HIDDIM 512
#define OUTDIM 256
#define K0 768
#define K1 1024
#define NBLK 128
#define NTHR 512

/* smem layout (bytes) */
#define SM_W0   0
#define SM_W1   (SM_W0 + 384*16*8)           /* 49152  : wS0 384 rows x 16 ull */
#define SM_RED  (SM_W1 + 512*16*8)           /* 114688 : wS1 512 rows x 16 ull */
#define SM_EX   (SM_RED + 16*128*32)         /* 180224 */
#define SM_OACC (SM_EX + 4*128*32)           /* 196608 */
#define SM_WOUT (SM_OACC + 4*128*16)         /* 204800 */
#define SM_BS   (SM_WOUT + 512*16)           /* 212992 */
#define SMEM_BYTES (SM_BS + 256)             /* 213248 */

__device__ float g_xT[(size_t)SEQ*INDIM*BATCH];   /* [t][k][b] */
__device__ float g_h0[2][HIDDIM*BATCH];           /* [phase][j][b] */
__device__ float g_h1[2][HIDDIM*BATCH];
__device__ unsigned long long g_ex[2][NBLK][1024]; /* [layer][bid][(qi*128+b)*4+g] peer rows */
__device__ unsigned g_pf[NBLK];                   /* pairwise monotonic flags */
__device__ unsigned g_cnt;
__device__ unsigned g_gen;

typedef unsigned long long ull;

__device__ __forceinline__ ull PK(float x, float y){
    ull r; asm("mov.b64 %0, {%1, %2};" : "=l"(r) : "f"(x), "f"(y)); return r;
}
__device__ __forceinline__ float2 UPK(ull a){
    float2 f; asm("mov.b64 {%0, %1}, %2;" : "=f"(f.x), "=f"(f.y) : "l"(a)); return f;
}
#define FMA2(acc,a,w) asm("fma.rn.f32x2 %0, %1, %2, %0;" : "+l"(acc) : "l"(a), "l"(w))
#define ADD2(acc,b)   asm("add.rn.f32x2 %0, %0, %1;"     : "+l"(acc) : "l"(b))

__device__ __forceinline__ void stcg2(ull* p, ull a, ull b){
    asm volatile("st.global.cg.v2.u64 [%0], {%1,%2};" :: "l"(p), "l"(a), "l"(b) : "memory");
}
__device__ __forceinline__ ulonglong2 ldcg2(const ull* p){
    ulonglong2 r;
    asm volatile("ld.global.cg.v2.u64 {%0,%1}, [%2];" : "=l"(r.x), "=l"(r.y) : "l"(p) : "memory");
    return r;
}

__device__ __forceinline__ float sigf(float x){ return 1.0f/(1.0f+expf(-x)); }

__device__ __forceinline__ void grid_sync(){
    __syncthreads();
    if (threadIdx.x == 0){
        volatile unsigned* vg = &g_gen;
        unsigned gen = *vg;
        __threadfence();
        if (atomicAdd(&g_cnt, 1u) == NBLK-1u){
            atomicExch(&g_cnt, 0u);
            __threadfence();
            atomicAdd(&g_gen, 1u);
        } else {
            while (*vg == gen) { __nanosleep(20); }
        }
        __threadfence();
    }
    __syncthreads();
}

/* pairwise barrier: release own flag, acquire peer's (monotonic, replay-safe) */
__device__ __forceinline__ void pair_wait(int bid, int peer, unsigned target){
    __syncthreads();
    if (threadIdx.x == 0){
        __threadfence();
        atomicAdd(&g_pf[bid], 1u);
        while (*(volatile unsigned*)&g_pf[peer] < target) { __nanosleep(20); }
        __threadfence();
    }
    __syncthreads();
}

/* x [t][b][k] -> g_xT [t][k][b] */
__global__ void transpose_x(const float* __restrict__ x){
    __shared__ float tile[32][33];
    int t = blockIdx.x, k0 = blockIdx.y*32, b0 = blockIdx.z*32;
    const float* src = x + (size_t)t*BATCH*INDIM;
    #pragma unroll
    for (int i = threadIdx.y; i < 32; i += 8)
        tile[i][threadIdx.x] = src[(size_t)(b0+i)*INDIM + k0 + threadIdx.x];
    __syncthreads();
    float* dst = g_xT + (size_t)t*INDIM*BATCH;
    #pragma unroll
    for (int i = threadIdx.y; i < 32; i += 8)
        dst[(size_t)(k0+i)*BATCH + b0 + threadIdx.x] = tile[threadIdx.x][i];
}

__device__ __forceinline__ void load8(float v[8], const float* s){
    #pragma unroll
    for (int i = 0; i < 8; i++) v[i] = __ldcg(s + i*BATCH);
}

__device__ __forceinline__ void comp8(const float va[8], const ulonglong2* wr, ull* acc){
    #pragma unroll
    for (int r = 0; r < 8; r++){
        ull vv = PK(va[r], va[r]);
        const ulonglong2* w = wr + r*8;
        #pragma unroll
        for (int j = 0; j < 8; j++){
            ulonglong2 w2 = w[j];
            FMA2(acc[2*j], vv, w2.x); FMA2(acc[2*j+1], vv, w2.y);
        }
    }
}

__device__ __forceinline__ void comp8o(const float va[8], const ulonglong2* wr, ull* acc,
                                       ull& o01, ull& o23, const ulonglong2* wo){
    #pragma unroll
    for (int r = 0; r < 8; r++){
        ull vv = PK(va[r], va[r]);
        const ulonglong2* w = wr + r*8;
        #pragma unroll
        for (int j = 0; j < 8; j++){
            ulonglong2 w2 = w[j];
            FMA2(acc[2*j], vv, w2.x); FMA2(acc[2*j+1], vv, w2.y);
        }
        ulonglong2 wq = wo[r];
        FMA2(o01, vv, wq.x); FMA2(o23, vv, wq.y);
    }
}

__device__ __forceinline__ void run_seg(const float* src, int nch,
                                        const ulonglong2* w2, ull* acc){
    if (nch <= 0) return;
    float va[8], vb[8];
    load8(va, src);
    for (int c = 0; c < nch; c += 2){
        if (c+1 < nch) load8(vb, src + (c+1)*8*BATCH);
        comp8(va, w2 + c*64, acc);
        if (c+1 >= nch) break;
        if (c+2 < nch) load8(va, src + (c+2)*8*BATCH);
        comp8(vb, w2 + (c+1)*64, acc);
    }
}

__device__ __forceinline__ void run_seg_out(const float* src, int nch,
                                            const ulonglong2* w2, ull* acc,
                                            ull& o01, ull& o23, const ulonglong2* wo){
    float va[8], vb[8];
    load8(va, src);
    for (int c = 0; c < nch; c += 2){
        if (c+1 < nch) load8(vb, src + (c+1)*8*BATCH);
        comp8o(va, w2 + c*64, acc, o01, o23, wo + c*8);
        if (c+1 >= nch) break;
        if (c+2 < nch) load8(va, src + (c+2)*8*BATCH);
        comp8o(vb, w2 + (c+1)*64, acc, o01, o23, wo + (c+1)*8);
    }
}

__global__ void __launch_bounds__(NTHR, 1) lstm_persist(
    const float* __restrict__ Wg0, const float* __restrict__ bg0,
    const float* __restrict__ Wg1, const float* __restrict__ bg1,
    const float* __restrict__ W_out, const float* __restrict__ b_out,
    float* __restrict__ out)
{
    extern __shared__ char smem[];
    ull*        wS0u = (ull*)(smem + SM_W0);          /* [row*16 + q*4 + gate] pair-packed */
    ull*        wS1u = (ull*)(smem + SM_W1);
    ulonglong2* redS2= (ulonglong2*)(smem + SM_RED);  /* [((g*4+q)*128+b)*2 + {0,1}] */
    ulonglong2* exS2 = (ulonglong2*)(smem + SM_EX);   /* [(q*128+b)*2 + {0,1}] */
    ulonglong2* oaccS2=(ulonglong2*)(smem + SM_OACC); /* [g*128+b] = (o01,o23) */
    ull*        wOutU= (ull*)(smem + SM_WOUT);        /* [k*2 + cp] col-pair packed */
    ull*        bSu  = (ull*)(smem + SM_BS);          /* [L*16 + q*4 + gate] */

    const int tid  = threadIdx.x, bid = blockIdx.x;
    const int rank = bid & 1;           /* K-half within pair */
    const int prank= rank ^ 1;
    const int peer = bid ^ 1;
    const int pair = bid >> 1;          /* unit-group: units pair*8..+7 */
    const int g    = tid >> 7;          /* intra-CTA K-subgroup 0..3 */
    const int b    = tid & 127;         /* batch (one per thread) */

    /* ---- weights (this rank's K-half, pair-packed) ---- */
    for (int idx = tid; idx < 384*16; idx += NTHR){
        int row = idx >> 4, q = (idx >> 2) & 3, gt = idx & 3;
        int k = rank*384 + row;
        int uA = pair*8 + 2*q;
        wS0u[idx] = PK(Wg0[(size_t)(gt*HIDDIM+uA)*K0 + k],
                       Wg0[(size_t)(gt*HIDDIM+uA+1)*K0 + k]);
    }
    for (int idx = tid; idx < 512*16; idx += NTHR){
        int row = idx >> 4, q = (idx >> 2) & 3, gt = idx & 3;
        int k = rank*512 + row;
        int uA = pair*8 + 2*q;
        wS1u[idx] = PK(Wg1[(size_t)(gt*HIDDIM+uA)*K1 + k],
                       Wg1[(size_t)(gt*HIDDIM+uA+1)*K1 + k]);
    }
    for (int idx = tid; idx < 1024; idx += NTHR){
        int k = idx >> 1, cp = idx & 1;
        int cA = pair*4 + cp*2;
        wOutU[idx] = PK(W_out[(size_t)cA*HIDDIM + k],
                        W_out[(size_t)(cA+1)*HIDDIM + k]);
    }
    if (tid < 32){
        int L = tid >> 4, q = (tid >> 2) & 3, gt = tid & 3;
        int uA = pair*8 + 2*q;
        const float* bg = L ? bg1 : bg0;
        bSu[tid] = PK(bg[gt*HIDDIM+uA], bg[gt*HIDDIM+uA+1]);
    }
    const float4 bo4 = *(const float4*)(b_out + pair*4);

    /* zero this pair's h slices (owners: rank's 2 unit-pairs) */
    if (tid < 256){
        int qz = rank*2 + (tid >> 7), bz = tid & 127;
        int uA = pair*8 + 2*qz;
        #pragma unroll
        for (int ph = 0; ph < 2; ph++){
            g_h0[ph][uA*BATCH+bz] = 0.f; g_h0[ph][(uA+1)*BATCH+bz] = 0.f;
            g_h1[ph][uA*BATCH+bz] = 0.f; g_h1[ph][(uA+1)*BATCH+bz] = 0.f;
        }
    }
    float C0a=0.f, C0b=0.f, C1a=0.f, C1b=0.f;
    float h0a=0.f, h0b=0.f, h1a=0.f, h1b=0.f;

    grid_sync();
    const unsigned pfb = *(volatile unsigned*)&g_pf[bid];  /* own flag == peer's (equal each run) */

    const size_t OB = (size_t)SEQ*BATCH*OUTDIM;
    const int qsel = rank*2 + (tid >> 7);     /* epilogue unit-pair (tid<256) */
    const int be   = tid & 127;
    const int uA   = pair*8 + 2*qsel;
    const int qi   = tid >> 7;                /* local row idx in peer's g_ex */

    for (int t = 0; t < SEQ; t++){
        const int cw = t & 1, pv = cw ^ 1;
        ull acc[16];

        /* ============ layer 0: K-half partials ============ */
        {
            #pragma unroll
            for (int i = 0; i < 16; i++) acc[i] = 0ull;
            const float* xb  = g_xT + (size_t)t*INDIM*BATCH;
            const float* h0p = g_h0[pv];
            int base  = rank*384 + g*96;
            int xrows = 256 - base;
            if (xrows < 0) xrows = 0; if (xrows > 96) xrows = 96;
            const ulonglong2* wloc = (const ulonglong2*)wS0u + g*96*8;
            run_seg(xb + (size_t)base*BATCH + b, xrows >> 3, wloc, acc);
            run_seg(h0p + (size_t)(base + xrows - 256)*BATCH + b,
                    (96 - xrows) >> 3, wloc + (xrows >> 3)*64, acc);
        }
        {
            ulonglong2* rs = redS2 + ((g*4)*128 + b)*2;
            #pragma unroll
            for (int q = 0; q < 4; q++){
                rs[q*256]     = make_ulonglong2(acc[q*4+0], acc[q*4+1]);
                rs[q*256 + 1] = make_ulonglong2(acc[q*4+2], acc[q*4+3]);
            }
        }
        __syncthreads();
        {   /* merge 4 groups; own rows -> exS, peer rows -> g_ex[0][bid] */
            int qm = tid >> 7, bm = tid & 127;
            ull sf=0, si=0, sc=0, so=0;
            #pragma unroll
            for (int gg = 0; gg < 4; gg++){
                const ulonglong2* e = redS2 + ((gg*4+qm)*128 + bm)*2;
                ulonglong2 e0 = e[0], e1 = e[1];
                ADD2(sf, e0.x); ADD2(si, e0.y); ADD2(sc, e1.x); ADD2(so, e1.y);
            }
            if ((qm >> 1) == rank){
                ulonglong2* x = exS2 + (qm*128 + bm)*2;
                x[0] = make_ulonglong2(sf, si); x[1] = make_ulonglong2(sc, so);
            } else {
                ull* d = &g_ex[0][bid][((qm & 1)*128 + bm)*4];
                stcg2(d, sf, si); stcg2(d+2, sc, so);
            }
        }
        pair_wait(bid, peer, pfb + 2*t + 1);
        if (tid < 256){  /* epilogue L0: own exS + peer g_ex */
            int idx = (qsel*128 + be)*2;
            ulonglong2 l0 = exS2[idx], l1 = exS2[idx+1];
            const ull* pe = &g_ex[0][peer][(qi*128 + be)*4];
            ulonglong2 p0 = ldcg2(pe), p1 = ldcg2(pe+2);
            ull sf=l0.x, si=l0.y, sc=l1.x, so=l1.y;
            ADD2(sf, p0.x); ADD2(si, p0.y); ADD2(sc, p1.x); ADD2(so, p1.y);
            ADD2(sf, bSu[qsel*4+0]); ADD2(si, bSu[qsel*4+1]);
            ADD2(sc, bSu[qsel*4+2]); ADD2(so, bSu[qsel*4+3]);
            float2 f2=UPK(sf), i2=UPK(si), c2=UPK(sc), o2=UPK(so);
            C0a = sigf(f2.x)*C0a + sigf(i2.x)*tanhf(c2.x);
            h0a = sigf(o2.x)*tanhf(C0a);
            C0b = sigf(f2.y)*C0b + sigf(i2.y)*tanhf(c2.y);
            h0b = sigf(o2.y)*tanhf(C0b);
            g_h0[cw][uA*BATCH + be]     = h0a;
            g_h0[cw][(uA+1)*BATCH + be] = h0b;
        }

        grid_sync();   /* the single per-step grid barrier (h0 broadcast) */

        /* ============ layer 1: K-half partials (+out fusion on rank1) ============ */
        ull o01 = 0, o23 = 0;
        {
            #pragma unroll
            for (int i = 0; i < 16; i++) acc[i] = 0ull;
            const float* src1 = ((rank == 0) ? g_h0[cw] : g_h1[pv])
                                + (size_t)(g*128)*BATCH + b;
            const ulonglong2* wloc = (const ulonglong2*)wS1u + g*128*8;
            if (rank == 1 && t > 0)
                run_seg_out(src1, 16, wloc, acc, o01, o23,
                            (const ulonglong2*)wOutU + g*128);
            else
                run_seg(src1, 16, wloc, acc);
        }
        {
            ulonglong2* rs = redS2 + ((g*4)*128 + b)*2;
            #pragma unroll
            for (int q = 0; q < 4; q++){
                rs[q*256]     = make_ulonglong2(acc[q*4+0], acc[q*4+1]);
                rs[q*256 + 1] = make_ulonglong2(acc[q*4+2], acc[q*4+3]);
            }
            if (rank == 1) oaccS2[g*128 + b] = make_ulonglong2(o01, o23);
        }
        __syncthreads();
        {
            int qm = tid >> 7, bm = tid & 127;
            ull sf=0, si=0, sc=0, so=0;
            #pragma unroll
            for (int gg = 0; gg < 4; gg++){
                const ulonglong2* e = redS2 + ((gg*4+qm)*128 + bm)*2;
                ulonglong2 e0 = e[0], e1 = e[1];
                ADD2(sf, e0.x); ADD2(si, e0.y); ADD2(sc, e1.x); ADD2(so, e1.y);
            }
            if ((qm >> 1) == rank){
                ulonglong2* x = exS2 + (qm*128 + bm)*2;
                x[0] = make_ulonglong2(sf, si); x[1] = make_ulonglong2(sc, so);
            } else {
                ull* d = &g_ex[1][bid][((qm & 1)*128 + bm)*4];
                stcg2(d, sf, si); stcg2(d+2, sc, so);
            }
        }
        pair_wait(bid, peer, pfb + 2*t + 2);
        if (tid < 256){  /* epilogue L1 */
            int idx = (qsel*128 + be)*2;
            ulonglong2 l0 = exS2[idx], l1 = exS2[idx+1];
            const ull* pe = &g_ex[1][peer][(qi*128 + be)*4];
            ulonglong2 p0 = ldcg2(pe), p1 = ldcg2(pe+2);
            ull sf=l0.x, si=l0.y, sc=l1.x, so=l1.y;
            ADD2(sf, p0.x); ADD2(si, p0.y); ADD2(sc, p1.x); ADD2(so, p1.y);
            ADD2(sf, bSu[16+qsel*4+0]); ADD2(si, bSu[16+qsel*4+1]);
            ADD2(sc, bSu[16+qsel*4+2]); ADD2(so, bSu[16+qsel*4+3]);
            float2 f2=UPK(sf), i2=UPK(si), c2=UPK(sc), o2=UPK(so);
            C1a = sigf(f2.x)*C1a + sigf(i2.x)*tanhf(c2.x);
            h1a = sigf(o2.x)*tanhf(C1a);
            C1b = sigf(f2.y)*C1b + sigf(i2.y)*tanhf(c2.y);
            h1b = sigf(o2.y)*tanhf(C1b);
            g_h1[cw][uA*BATCH + be]     = h1a;
            g_h1[cw][(uA+1)*BATCH + be] = h1b;
        }
        if (rank == 1 && t > 0 && tid < 128){  /* out[t-1], 4 cols of this pair */
            ulonglong2 s = oaccS2[tid];
            ull a01 = s.x, a23 = s.y;
            #pragma unroll
            for (int gg = 1; gg < 4; gg++){
                s = oaccS2[gg*128 + tid];
                ADD2(a01, s.x); ADD2(a23, s.y);
            }
            float2 r01 = UPK(a01), r23 = UPK(a23);
            float4 ov = make_float4(r01.x + bo4.x, r01.y + bo4.y,
                                    r23.x + bo4.z, r23.y + bo4.w);
            *(float4*)(out + ((size_t)(t-1)*BATCH + tid)*OUTDIM + pair*4) = ov;
        }
    }

    grid_sync();
    /* out[SEQ-1] (rank1, 4 cols) */
    if (rank == 1 && tid < 128){
        ull a01 = 0, a23 = 0;
        const float* h1f = g_h1[(SEQ-1)&1];
        const ulonglong2* wo = (const ulonglong2*)wOutU;
        #pragma unroll 4
        for (int j = 0; j < HIDDIM; j++){
            float v = __ldcg(h1f + j*BATCH + tid);
            ull vv = PK(v, v);
            ulonglong2 wq = wo[j];
            FMA2(a01, vv, wq.x); FMA2(a23, vv, wq.y);
        }
        float2 r01 = UPK(a01), r23 = UPK(a23);
        float4 ov = make_float4(r01.x + bo4.x, r01.y + bo4.y,
                                r23.x + bo4.z, r23.y + bo4.w);
        *(float4*)(out + ((size_t)(SEQ-1)*BATCH + tid)*OUTDIM + pair*4) = ov;
    }
    /* final states: [B][HID] each, order h_0, C_0, h_1, C_1 (owner threads) */
    if (tid < 256){
        size_t rA = (size_t)be*HIDDIM + uA, rB = rA + 1;
        out[OB          + rA] = h0a;  out[OB          + rB] = h0b;
        out[OB +  65536 + rA] = C0a;  out[OB +  65536 + rB] = C0b;
        out[OB + 131072 + rA] = h1a;  out[OB + 131072 + rB] = h1b;
        out[OB + 196608 + rA] = C1a;  out[OB + 196608 + rB] = C1b;
    }
}

extern "C" void kernel_launch(void* const* d_in, const int* in_sizes, int n_in,
                              void* d_out, int out_size)
{
    (void)in_sizes; (void)n_in; (void)out_size;
    const float* x     = (const float*)d_in[0];
    const float* Wg0   = (const float*)d_in[1];
    const float* bg0   = (const float*)d_in[2];
    const float* Wg1   = (const float*)d_in[3];
    const float* bg1   = (const float*)d_in[4];
    const float* W_out = (const float*)d_in[5];
    const float* b_out = (const float*)d_in[6];

    cudaFuncSetAttribute(lstm_persist,
                         cudaFuncAttributeMaxDynamicSharedMemorySize, SMEM_BYTES);

    transpose_x<<<dim3(SEQ, INDIM/32, BATCH/32), dim3(32, 8)>>>(x);
    lstm_persist<<<NBLK, NTHR, SMEM_BYTES>>>(Wg0, bg0, Wg1, bg1, W_out, b_out,
                                             (float*)d_out);
}

// round 15
// speedup vs baseline: 1.0726x; 1.0726x over previous
#include <cuda_runtime.h>
#include <cstdint>
#include <math.h>

#define SEQ 512
#define BATCH 128
#define INDIM 256
#define HIDDIM 512
#define OUTDIM 256
#define K0 768
#define K1 1024
#define NBLK 128
#define NTHR 1024

/* smem layout (bytes) */
#define SM_W0   0
#define SM_W1   (SM_W0 + K0*4*16)            /* 49152  */
#define SM_RED  (SM_W1 + K1*4*16)            /* 114688 */
#define SM_OACC (SM_RED + 8*512*16)          /* 180224 : 64KB partials */
#define SM_WOUT (SM_OACC + 4*128*8)          /* 184320 */
#define SM_BS   (SM_WOUT + 512*8)            /* 188416 */
#define SMEM_BYTES (SM_BS + 256)             /* 188672 */

__device__ float g_xT[(size_t)SEQ*INDIM*BATCH];   /* [t][k][b] */
__device__ float g_h0[2][HIDDIM*BATCH];           /* [phase][j][b] */
__device__ float g_h1[2][HIDDIM*BATCH];
__device__ unsigned g_cnt;
__device__ unsigned g_gen;

typedef unsigned long long ull;

__device__ __forceinline__ ull PK(float x, float y){
    ull r; asm("mov.b64 %0, {%1, %2};" : "=l"(r) : "f"(x), "f"(y)); return r;
}
__device__ __forceinline__ float2 UPK(ull a){
    float2 f; asm("mov.b64 {%0, %1}, %2;" : "=f"(f.x), "=f"(f.y) : "l"(a)); return f;
}
#define FMA2(acc,a,w) asm("fma.rn.f32x2 %0, %1, %2, %0;" : "+l"(acc) : "l"(a), "l"(w))
#define ADD2(acc,b)   asm("add.rn.f32x2 %0, %0, %1;"     : "+l"(acc) : "l"(b))

__device__ __forceinline__ float sigf(float x){ return 1.0f/(1.0f+expf(-x)); }

__device__ __forceinline__ void grid_sync(){
    __syncthreads();
    if (threadIdx.x == 0){
        volatile unsigned* vg = &g_gen;
        unsigned gen = *vg;
        __threadfence();
        if (atomicAdd(&g_cnt, 1u) == NBLK-1u){
            atomicExch(&g_cnt, 0u);
            __threadfence();
            atomicAdd(&g_gen, 1u);
        } else {
            while (*vg == gen) { __nanosleep(20); }
        }
        __threadfence();
    }
    __syncthreads();
}

/* x [t][b][k] -> g_xT [t][k][b] */
__global__ void transpose_x(const float* __restrict__ x){
    __shared__ float tile[32][33];
    int t = blockIdx.x, k0 = blockIdx.y*32, b0 = blockIdx.z*32;
    const float* src = x + (size_t)t*BATCH*INDIM;
    #pragma unroll
    for (int i = threadIdx.y; i < 32; i += 8)
        tile[i][threadIdx.x] = src[(size_t)(b0+i)*INDIM + k0 + threadIdx.x];
    __syncthreads();
    float* dst = g_xT + (size_t)t*INDIM*BATCH;
    #pragma unroll
    for (int i = threadIdx.y; i < 32; i += 8)
        dst[(size_t)(k0+i)*BATCH + b0 + threadIdx.x] = tile[threadIdx.x][i];
}

__device__ __forceinline__ void load8(float v[8], const float* s){
    #pragma unroll
    for (int i = 0; i < 8; i++) v[i] = __ldcg(s + i*BATCH);
}

/* 8 rows: per row 4x LDS.128 (unit gate-pairs) + 8 FMA2 */
__device__ __forceinline__ void comp8(const float va[8], const ulonglong2* wr,
                                      ull* fi, ull* co){
    #pragma unroll
    for (int r = 0; r < 8; r++){
        ull vv = PK(va[r], va[r]);
        const ulonglong2* w = wr + r*4;
        #pragma unroll
        for (int u = 0; u < 4; u++){
            ulonglong2 w2 = w[u];
            FMA2(fi[u], vv, w2.x); FMA2(co[u], vv, w2.y);
        }
    }
}

__device__ __forceinline__ void comp8o(const float va[8], const ulonglong2* wr,
                                       ull* fi, ull* co, ull& o, const ull* wo){
    #pragma unroll
    for (int r = 0; r < 8; r++){
        ull vv = PK(va[r], va[r]);
        const ulonglong2* w = wr + r*4;
        #pragma unroll
        for (int u = 0; u < 4; u++){
            ulonglong2 w2 = w[u];
            FMA2(fi[u], vv, w2.x); FMA2(co[u], vv, w2.y);
        }
        FMA2(o, vv, wo[r]);
    }
}

__device__ __forceinline__ void run_seg(const float* src, int nch,
                                        const ulonglong2* w2, ull* fi, ull* co){
    if (nch <= 0) return;
    float va[8], vb[8];
    load8(va, src);
    for (int c = 0; c < nch; c += 2){
        if (c+1 < nch) load8(vb, src + (c+1)*8*BATCH);
        comp8(va, w2 + c*32, fi, co);
        if (c+1 >= nch) break;
        if (c+2 < nch) load8(va, src + (c+2)*8*BATCH);
        comp8(vb, w2 + (c+1)*32, fi, co);
    }
}

__device__ __forceinline__ void run_seg_out(const float* src, int nch,
                                            const ulonglong2* w2, ull* fi, ull* co,
                                            ull& o, const ull* wo){
    float va[8], vb[8];
    load8(va, src);
    for (int c = 0; c < nch; c += 2){
        if (c+1 < nch) load8(vb, src + (c+1)*8*BATCH);
        comp8o(va, w2 + c*32, fi, co, o, wo + c*8);
        if (c+1 >= nch) break;
        if (c+2 < nch) load8(va, src + (c+2)*8*BATCH);
        comp8o(vb, w2 + (c+1)*32, fi, co, o, wo + (c+1)*8);
    }
}

__global__ void __launch_bounds__(NTHR, 1) lstm_persist(
    const float* __restrict__ Wg0, const float* __restrict__ bg0,
    const float* __restrict__ Wg1, const float* __restrict__ bg1,
    const float* __restrict__ W_out, const float* __restrict__ b_out,
    float* __restrict__ out)
{
    extern __shared__ char smem[];
    ulonglong2* wS0  = (ulonglong2*)(smem + SM_W0);   /* [k*4+u] = {(wf,wi),(wc,wo)} */
    ulonglong2* wS1  = (ulonglong2*)(smem + SM_W1);
    ulonglong2* redS = (ulonglong2*)(smem + SM_RED);  /* [g*512 + u*128 + b] = (fi,co) */
    ull*        oaccS= (ull*)(smem + SM_OACC);        /* [(g-4)*128 + b] */
    ull*        wOutS= (ull*)(smem + SM_WOUT);        /* [k] = (w_c0, w_c1) */
    ulonglong2* bS   = (ulonglong2*)(smem + SM_BS);   /* [L*4+u] = (bfi,bco) */

    const int tid = threadIdx.x, bid = blockIdx.x;
    const int g   = tid >> 7;           /* K-group 0..7 */
    const int b   = tid & 127;          /* batch element */
    const int uo  = (tid >> 7) & 3;     /* owner unit (tid<512) */
    const int bo  = tid & 127;          /* owner batch  (tid<512) */

    /* ---- weights / consts -> smem ---- */
    for (int idx = tid; idx < K0*4; idx += NTHR){
        int k = idx >> 2, uu = bid*4 + (idx & 3);
        float wf = Wg0[(size_t)(0*HIDDIM+uu)*K0 + k];
        float wi = Wg0[(size_t)(1*HIDDIM+uu)*K0 + k];
        float wc = Wg0[(size_t)(2*HIDDIM+uu)*K0 + k];
        float wo = Wg0[(size_t)(3*HIDDIM+uu)*K0 + k];
        wS0[idx] = make_ulonglong2(PK(wf,wi), PK(wc,wo));
    }
    for (int idx = tid; idx < K1*4; idx += NTHR){
        int k = idx >> 2, uu = bid*4 + (idx & 3);
        float wf = Wg1[(size_t)(0*HIDDIM+uu)*K1 + k];
        float wi = Wg1[(size_t)(1*HIDDIM+uu)*K1 + k];
        float wc = Wg1[(size_t)(2*HIDDIM+uu)*K1 + k];
        float wo = Wg1[(size_t)(3*HIDDIM+uu)*K1 + k];
        wS1[idx] = make_ulonglong2(PK(wf,wi), PK(wc,wo));
    }
    for (int k = tid; k < HIDDIM; k += NTHR)
        wOutS[k] = PK(W_out[(size_t)(bid*2)*HIDDIM + k],
                      W_out[(size_t)(bid*2+1)*HIDDIM + k]);
    if (tid < 8){
        int L = tid >> 2, u = tid & 3, ug = bid*4 + u;
        const float* bg = L ? bg1 : bg0;
        bS[tid] = make_ulonglong2(PK(bg[ug], bg[HIDDIM+ug]),
                                  PK(bg[2*HIDDIM+ug], bg[3*HIDDIM+ug]));
    }
    if (tid < 512){
        int u = bid*4 + uo;
        #pragma unroll
        for (int ph = 0; ph < 2; ph++){
            g_h0[ph][u*BATCH+bo] = 0.f;
            g_h1[ph][u*BATCH+bo] = 0.f;
        }
    }
    float C0own = 0.f, C1own = 0.f, h0own = 0.f, h1own = 0.f;

    grid_sync();

    const size_t OB = (size_t)SEQ*BATCH*OUTDIM;
    const float2 bo2 = make_float2(b_out[bid*2], b_out[bid*2+1]);

    for (int t = 0; t < SEQ; t++){
        const int cw = t & 1, pv = cw ^ 1;
        ull fi[4], co[4];

        /* ============ layer 0: 8-way K-split, direct LDG ============ */
        {
            #pragma unroll
            for (int u = 0; u < 4; u++){ fi[u] = 0ull; co[u] = 0ull; }
            const float* xb  = g_xT + (size_t)t*INDIM*BATCH;
            const float* h0p = g_h0[pv];
            int base  = g*96;
            int xrows = 256 - base;
            if (xrows < 0) xrows = 0; if (xrows > 96) xrows = 96;
            const ulonglong2* wloc = wS0 + base*4;
            run_seg(xb + (size_t)base*BATCH + b, xrows >> 3, wloc, fi, co);
            run_seg(h0p + (size_t)(base + xrows - 256)*BATCH + b,
                    (96 - xrows) >> 3, wloc + (xrows >> 3)*32, fi, co);
        }
        {
            ulonglong2* rs = redS + g*512 + b;
            #pragma unroll
            for (int u = 0; u < 4; u++)
                rs[u*128] = make_ulonglong2(fi[u], co[u]);
        }
        __syncthreads();
        if (tid < 512){
            ull sf = 0, sc = 0;
            int slot = uo*128 + bo;
            #pragma unroll
            for (int gg = 0; gg < 8; gg++){
                ulonglong2 r = redS[gg*512 + slot];
                ADD2(sf, r.x); ADD2(sc, r.y);
            }
            ulonglong2 bb = bS[uo];
            ADD2(sf, bb.x); ADD2(sc, bb.y);
            float2 q1 = UPK(sf), q2 = UPK(sc);
            C0own = sigf(q1.x)*C0own + sigf(q1.y)*tanhf(q2.x);
            h0own = sigf(q2.y)*tanhf(C0own);
            g_h0[cw][(bid*4+uo)*BATCH + bo] = h0own;
        }

        grid_sync();   /* the single per-step grid barrier */

        /* ============ layer 1 (+ fused out[t-1] in groups 4-7) ============ */
        const float* h0c = g_h0[cw];
        const float* h1p = g_h1[pv];
        #pragma unroll
        for (int u = 0; u < 4; u++){ fi[u] = 0ull; co[u] = 0ull; }
        ull o = 0;
        {
            const float* src1 = ((g < 4) ? h0c + (size_t)(g*128)*BATCH
                                         : h1p + (size_t)((g-4)*128)*BATCH) + b;
            const ulonglong2* wloc = wS1 + (g*128)*4;
            if (g >= 4 && t > 0)
                run_seg_out(src1, 16, wloc, fi, co, o, wOutS + (g-4)*128);
            else
                run_seg(src1, 16, wloc, fi, co);
        }
        {
            ulonglong2* rs = redS + g*512 + b;
            #pragma unroll
            for (int u = 0; u < 4; u++)
                rs[u*128] = make_ulonglong2(fi[u], co[u]);
            if (g >= 4 && t > 0) oaccS[(g-4)*128 + b] = o;
        }
        __syncthreads();
        if (tid < 512){
            ull sf = 0, sc = 0;
            int slot = uo*128 + bo;
            #pragma unroll
            for (int gg = 0; gg < 8; gg++){
                ulonglong2 r = redS[gg*512 + slot];
                ADD2(sf, r.x); ADD2(sc, r.y);
            }
            ulonglong2 bb = bS[4+uo];
            ADD2(sf, bb.x); ADD2(sc, bb.y);
            float2 q1 = UPK(sf), q2 = UPK(sc);
            C1own = sigf(q1.x)*C1own + sigf(q1.y)*tanhf(q2.x);
            h1own = sigf(q2.y)*tanhf(C1own);
            g_h1[cw][(bid*4+uo)*BATCH + bo] = h1own;
        }
        if (t > 0 && tid >= 512 && tid < 640){  /* out[t-1] merge on idle warps */
            int bb2 = tid - 512;
            ull s = oaccS[bb2];
            #pragma unroll
            for (int gg = 1; gg < 4; gg++) ADD2(s, oaccS[gg*128 + bb2]);
            float2 r = UPK(s);
            *(float2*)(out + ((size_t)(t-1)*BATCH + bb2)*OUTDIM + bid*2) =
                make_float2(r.x + bo2.x, r.y + bo2.y);
        }
        __syncthreads();   /* protect redS/oaccS before next step's stores */
    }

    grid_sync();
    /* out[SEQ-1] */
    if (tid < 128){
        ull o = 0;
        const float* h1f = g_h1[(SEQ-1)&1];
        #pragma unroll 4
        for (int j = 0; j < HIDDIM; j++){
            float v = __ldcg(h1f + j*BATCH + tid);
            FMA2(o, PK(v, v), wOutS[j]);
        }
        float2 r = UPK(o);
        *(float2*)(out + ((size_t)(SEQ-1)*BATCH + tid)*OUTDIM + bid*2) =
            make_float2(r.x + bo2.x, r.y + bo2.y);
    }
    /* final states: [B][HID] each, order h_0, C_0, h_1, C_1 (owner threads) */
    if (tid < 512){
        size_t r = (size_t)bo*HIDDIM + bid*4 + uo;
        out[OB          + r] = h0own;
        out[OB +  65536 + r] = C0own;
        out[OB + 131072 + r] = h1own;
        out[OB + 196608 + r] = C1own;
    }
}

extern "C" void kernel_launch(void* const* d_in, const int* in_sizes, int n_in,
                              void* d_out, int out_size)
{
    (void)in_sizes; (void)n_in; (void)out_size;
    const float* x     = (const float*)d_in[0];
    const float* Wg0   = (const float*)d_in[1];
    const float* bg0   = (const float*)d_in[2];
    const float* Wg1   = (const float*)d_in[3];
    const float* bg1   = (const float*)d_in[4];
    const float* W_out = (const float*)d_in[5];
    const float* b_out = (const float*)d_in[6];

    cudaFuncSetAttribute(lstm_persist,
                         cudaFuncAttributeMaxDynamicSharedMemorySize, SMEM_BYTES);

    transpose_x<<<dim3(SEQ, INDIM/32, BATCH/32), dim3(32, 8)>>>(x);
    lstm_persist<<<NBLK, NTHR, SMEM_BYTES>>>(Wg0, bg0, Wg1, bg1, W_out, b_out,
                                             (float*)d_out);
}

// round 17
// speedup vs baseline: 2.2206x; 2.0703x over previous
#include <cuda_runtime.h>
#include <cuda_fp16.h>
#include <cstdint>
#include <math.h>

#define SEQ 512
#define BATCH 128
#define HID 512
#define OUTDIM 256
#define NBLK 128
#define NTHR 512

/* smem: weights row-major fp16, padded pitches (row-step = 4 banks) */
#define P0 1552              /* wS0: 16 x 776 fp16  */
#define P1 2064              /* wS1: 16 x 1032 fp16 */
#define PO 1040              /* wOut:16 x 520 fp16  */
#define PV 272               /* v buf: 64 x 136 fp16 per chunk */
#define SM_W0  0             /* 24832 */
#define SM_W1  24832         /* 33024 */
#define SM_WO  57856         /* 16640 */
#define SM_BS0 74496
#define SM_BS1 74560
#define SM_VB  74752         /* 2 x 17408 */
#define SMEM_BYTES 109696

__device__ __half g_xh[(size_t)SEQ*256*BATCH];   /* [t][k][b] fp16 */
__device__ __half g_h0h[2][HID*BATCH];           /* [phase][j][b] */
__device__ __half g_h1h[2][HID*BATCH];
__device__ unsigned g_cnt, g_gen;

__device__ __forceinline__ unsigned smem_u32(const void* p){
    unsigned a;
    asm("{ .reg .u64 t; cvta.to.shared.u64 t, %1; cvt.u32.u64 %0, t; }" : "=r"(a) : "l"(p));
    return a;
}
__device__ __forceinline__ void cpa16s(unsigned d, const void* src){
    asm volatile("cp.async.cg.shared.global [%0], [%1], 16;" :: "r"(d), "l"(src) : "memory");
}
#define CP_COMMIT() asm volatile("cp.async.commit_group;" ::: "memory")
#define CP_WAIT0()  asm volatile("cp.async.wait_group 0;" ::: "memory")

#define LDSM4(r0,r1,r2,r3,addr) \
    asm volatile("ldmatrix.sync.aligned.m8n8.x4.shared.b16 {%0,%1,%2,%3}, [%4];" \
        : "=r"(r0),"=r"(r1),"=r"(r2),"=r"(r3) : "r"(addr))
#define LDSM2T(r0,r1,addr) \
    asm volatile("ldmatrix.sync.aligned.m8n8.x2.trans.shared.b16 {%0,%1}, [%2];" \
        : "=r"(r0),"=r"(r1) : "r"(addr))

__device__ __forceinline__ void mma16816(float* d, unsigned a0, unsigned a1,
                                         unsigned a2, unsigned a3,
                                         unsigned b0, unsigned b1){
    asm volatile("mma.sync.aligned.m16n8k16.row.col.f32.f16.f16.f32 "
        "{%0,%1,%2,%3}, {%4,%5,%6,%7}, {%8,%9}, {%0,%1,%2,%3};"
        : "+f"(d[0]),"+f"(d[1]),"+f"(d[2]),"+f"(d[3])
        : "r"(a0),"r"(a1),"r"(a2),"r"(a3), "r"(b0),"r"(b1));
}

/* stage one 64x128 fp16 chunk (16KB) into padded smem buffer */
__device__ __forceinline__ void stage(unsigned dst, const __half* src, int tid){
    #pragma unroll
    for (int i = 0; i < 2; i++){
        int c = tid + i*512;
        cpa16s(dst + (c>>4)*PV + (c&15)*16, (const char*)src + (size_t)c*16);
    }
    CP_COMMIT();
}

__device__ __forceinline__ float sigf(float x){ return 1.0f/(1.0f+expf(-x)); }

__device__ __forceinline__ void grid_sync(){
    __syncthreads();
    if (threadIdx.x == 0){
        volatile unsigned* vg = &g_gen;
        unsigned gen = *vg;
        __threadfence();
        if (atomicAdd(&g_cnt, 1u) == NBLK-1u){
            atomicExch(&g_cnt, 0u);
            __threadfence();
            atomicAdd(&g_gen, 1u);
        } else {
            while (*vg == gen) { __nanosleep(20); }
        }
        __threadfence();
    }
    __syncthreads();
}

/* x [t][b][k] fp32 -> g_xh [t][k][b] fp16 */
__global__ void convert_x(const float* __restrict__ x){
    __shared__ float tile[32][33];
    int t = blockIdx.x, k0 = blockIdx.y*32, b0 = blockIdx.z*32;
    const float* src = x + (size_t)t*BATCH*256;
    #pragma unroll
    for (int i = threadIdx.y; i < 32; i += 8)
        tile[i][threadIdx.x] = src[(size_t)(b0+i)*256 + k0 + threadIdx.x];
    __syncthreads();
    __half* dst = g_xh + (size_t)t*256*BATCH;
    #pragma unroll
    for (int i = threadIdx.y; i < 32; i += 8)
        dst[(size_t)(k0+i)*BATCH + b0 + threadIdx.x] = __float2half(tile[threadIdx.x][i]);
}

__global__ void __launch_bounds__(NTHR, 1) lstm_persist(
    const float* __restrict__ Wg0, const float* __restrict__ bg0,
    const float* __restrict__ Wg1, const float* __restrict__ bg1,
    const float* __restrict__ W_out, const float* __restrict__ b_out,
    float* __restrict__ out)
{
    extern __shared__ char smem[];
    const unsigned sb = smem_u32(smem);
    float* bs0 = (float*)(smem + SM_BS0);
    float* bs1 = (float*)(smem + SM_BS1);

    const int tid = threadIdx.x, bid = blockIdx.x;
    const int w   = tid >> 5;          /* warp = N-tile: batches 8w..8w+7 */
    const int l   = tid & 31;

    /* ---- weights -> smem fp16 (A rows r = gt*4 + u) ---- */
    for (int idx = tid; idx < 16*768; idx += NTHR){
        int r = idx / 768, k = idx % 768;
        float wv = Wg0[(size_t)((r>>2)*HID + bid*4 + (r&3))*768 + k];
        *(__half*)(smem + SM_W0 + r*P0 + k*2) = __float2half(wv);
    }
    for (int idx = tid; idx < 16*1024; idx += NTHR){
        int r = idx >> 10, k = idx & 1023;
        float wv = Wg1[(size_t)((r>>2)*HID + bid*4 + (r&3))*1024 + k];
        *(__half*)(smem + SM_W1 + r*P1 + k*2) = __float2half(wv);
    }
    for (int idx = tid; idx < 16*PO/4; idx += NTHR)
        ((unsigned*)(smem + SM_WO))[idx] = 0u;
    __syncthreads();
    for (int idx = tid; idx < 2*512; idx += NTHR){
        int r = idx >> 9, k = idx & 511;
        float wv = W_out[(size_t)(bid*2 + r)*HID + k];
        *(__half*)(smem + SM_WO + r*PO + k*2) = __float2half(wv);
    }
    if (tid < 16){
        bs0[tid] = bg0[(tid>>2)*HID + bid*4 + (tid&3)];
        bs1[tid] = bg1[(tid>>2)*HID + bid*4 + (tid&3)];
    }
    /* zero h slices (fresh per replay): thread -> (u, b) */
    {
        int u = tid >> 7, b = tid & 127;
        int j = (bid*4+u)*BATCH + b;
        g_h0h[0][j] = __float2half(0.f); g_h0h[1][j] = __float2half(0.f);
        g_h1h[0][j] = __float2half(0.f); g_h1h[1][j] = __float2half(0.f);
    }
    grid_sync();

    /* per-thread address constants */
    const unsigned aRow0 = sb + SM_W0 + (unsigned)(l&15)*P0;
    const unsigned aRow1 = sb + SM_W1 + (unsigned)(l&15)*P1;
    const unsigned aRowO = sb + SM_WO + (unsigned)(l&15)*PO;
    const unsigned aSel  = (unsigned)((l>>4)*8);
    const unsigned bRow  = (unsigned)(l&15)*PV + (unsigned)(w<<4);
    const unsigned vb    = sb + SM_VB;

    const size_t OB = (size_t)SEQ*BATCH*OUTDIM;
    const float2 bo2 = make_float2(b_out[bid*2], b_out[bid*2+1]);

    /* cell state in fragment-owner lanes (l < 16) */
    float C0a=0.f, C0b=0.f, C1a=0.f, C1b=0.f;
    float h0a=0.f, h0b=0.f, h1a=0.f, h1b=0.f;

    for (int t = 0; t < SEQ; t++){
        const int cw = t & 1, pv = cw ^ 1;
        const __half* xb  = g_xh + (size_t)t*256*BATCH;
        const __half* h0p = g_h0h[pv];
        unsigned a0,a1,a2,a3,b0,b1;

        /* ================= layer 0: 12 chunks of 64 k-rows ================= */
        float ga[4] = {0.f,0.f,0.f,0.f};
        stage(vb, xb, tid);
        for (int c = 0; c < 12; c++){
            CP_WAIT0();
            __syncthreads();
            if (c < 11){
                const __half* s = (c+1 < 4) ? xb + (size_t)(c+1)*64*BATCH
                                            : h0p + (size_t)(c-3)*64*BATCH;
                stage(vb + ((c+1)&1)*17408, s, tid);
            }
            unsigned bbase = vb + (c&1)*17408 + bRow;
            unsigned kg = (unsigned)(c*64);
            #pragma unroll
            for (int kt = 0; kt < 4; kt++){
                LDSM4(a0,a1,a2,a3, aRow0 + ((kg + kt*16 + aSel)<<1));
                LDSM2T(b0,b1, bbase + kt*16*PV);
                mma16816(ga, a0,a1,a2,a3, b0,b1);
            }
        }
        {   /* epilogue L0 */
            float q0 = __shfl_down_sync(0xffffffffu, ga[0], 16);
            float q1 = __shfl_down_sync(0xffffffffu, ga[1], 16);
            float q2 = __shfl_down_sync(0xffffffffu, ga[2], 16);
            float q3 = __shfl_down_sync(0xffffffffu, ga[3], 16);
            if (l < 16){
                int r1 = l >> 2;
                int b0i = (w<<3) + ((l&3)<<1);
                float f = sigf(ga[0] + bs0[r1]);
                float i = sigf(q0    + bs0[r1+4]);
                float cc= tanhf(ga[2] + bs0[r1+8]);
                float o = sigf(q2    + bs0[r1+12]);
                C0a = f*C0a + i*cc;  h0a = o*tanhf(C0a);
                f = sigf(ga[1] + bs0[r1]);
                i = sigf(q1    + bs0[r1+4]);
                cc= tanhf(ga[3] + bs0[r1+8]);
                o = sigf(q3    + bs0[r1+12]);
                C0b = f*C0b + i*cc;  h0b = o*tanhf(C0b);
                g_h0h[cw][(bid*4+r1)*BATCH + b0i]   = __float2half(h0a);
                g_h0h[cw][(bid*4+r1)*BATCH + b0i+1] = __float2half(h0b);
            }
        }

        grid_sync();   /* the single per-step grid barrier */

        /* ========= layer 1: 16 chunks (+ fused W_out A-tile on h1p chunks) ========= */
        const __half* h0c = g_h0h[cw];
        const __half* h1p = g_h1h[pv];
        float g1[4] = {0.f,0.f,0.f,0.f};
        float oa[4] = {0.f,0.f,0.f,0.f};
        stage(vb, h0c, tid);
        for (int c = 0; c < 16; c++){
            CP_WAIT0();
            __syncthreads();
            if (c < 15){
                const __half* s = (c+1 < 8) ? h0c + (size_t)(c+1)*64*BATCH
                                            : h1p + (size_t)(c-7)*64*BATCH;
                stage(vb + ((c+1)&1)*17408, s, tid);
            }
            unsigned bbase = vb + (c&1)*17408 + bRow;
            unsigned kg = (unsigned)(c*64);
            if (c < 8){
                #pragma unroll
                for (int kt = 0; kt < 4; kt++){
                    LDSM4(a0,a1,a2,a3, aRow1 + ((kg + kt*16 + aSel)<<1));
                    LDSM2T(b0,b1, bbase + kt*16*PV);
                    mma16816(g1, a0,a1,a2,a3, b0,b1);
                }
            } else {
                unsigned ko = (unsigned)((c-8)*64);
                #pragma unroll
                for (int kt = 0; kt < 4; kt++){
                    LDSM4(a0,a1,a2,a3, aRow1 + ((kg + kt*16 + aSel)<<1));
                    LDSM2T(b0,b1, bbase + kt*16*PV);
                    mma16816(g1, a0,a1,a2,a3, b0,b1);
                    LDSM4(a0,a1,a2,a3, aRowO + ((ko + kt*16 + aSel)<<1));
                    mma16816(oa, a0,a1,a2,a3, b0,b1);
                }
            }
        }
        {   /* epilogue L1 */
            float q0 = __shfl_down_sync(0xffffffffu, g1[0], 16);
            float q1 = __shfl_down_sync(0xffffffffu, g1[1], 16);
            float q2 = __shfl_down_sync(0xffffffffu, g1[2], 16);
            float q3 = __shfl_down_sync(0xffffffffu, g1[3], 16);
            if (l < 16){
                int r1 = l >> 2;
                int b0i = (w<<3) + ((l&3)<<1);
                float f = sigf(g1[0] + bs1[r1]);
                float i = sigf(q0    + bs1[r1+4]);
                float cc= tanhf(g1[2] + bs1[r1+8]);
                float o = sigf(q2    + bs1[r1+12]);
                C1a = f*C1a + i*cc;  h1a = o*tanhf(C1a);
                f = sigf(g1[1] + bs1[r1]);
                i = sigf(q1    + bs1[r1+4]);
                cc= tanhf(g1[3] + bs1[r1+8]);
                o = sigf(q3    + bs1[r1+12]);
                C1b = f*C1b + i*cc;  h1b = o*tanhf(C1b);
                g_h1h[cw][(bid*4+r1)*BATCH + b0i]   = __float2half(h1a);
                g_h1h[cw][(bid*4+r1)*BATCH + b0i+1] = __float2half(h1b);
            }
            if (t > 0 && l < 8){   /* out[t-1]: A2 rows 0/1 */
                int ocol = l >> 2;
                int b0i = (w<<3) + ((l&3)<<1);
                float boc = ocol ? bo2.y : bo2.x;
                size_t ob = ((size_t)(t-1)*BATCH + b0i)*OUTDIM + bid*2 + ocol;
                out[ob]          = oa[0] + boc;
                out[ob + OUTDIM] = oa[1] + boc;
            }
        }
        __syncthreads();   /* buffers reused by next step's staging */
    }

    grid_sync();
    /* out[SEQ-1] (SIMT) */
    if (tid < 128){
        const __half* h1f = g_h1h[(SEQ-1)&1];
        float o0 = 0.f, o1 = 0.f;
        #pragma unroll 4
        for (int j = 0; j < HID; j++){
            float v = __half2float(__ldcg(h1f + j*BATCH + tid));
            o0 += v * W_out[(size_t)(bid*2)*HID + j];
            o1 += v * W_out[(size_t)(bid*2+1)*HID + j];
        }
        *(float2*)(out + ((size_t)(SEQ-1)*BATCH + tid)*OUTDIM + bid*2) =
            make_float2(o0 + bo2.x, o1 + bo2.y);
    }
    /* final states: [B][HID] each, order h_0, C_0, h_1, C_1 (fragment owners) */
    if (l < 16){
        int r1 = l >> 2;
        int b0i = (w<<3) + ((l&3)<<1);
        size_t rA = (size_t)b0i*HID + bid*4 + r1;
        size_t rB = rA + HID;
        out[OB          + rA] = h0a;  out[OB          + rB] = h0b;
        out[OB +  65536 + rA] = C0a;  out[OB +  65536 + rB] = C0b;
        out[OB + 131072 + rA] = h1a;  out[OB + 131072 + rB] = h1b;
        out[OB + 196608 + rA] = C1a;  out[OB + 196608 + rB] = C1b;
    }
}

extern "C" void kernel_launch(void* const* d_in, const int* in_sizes, int n_in,
                              void* d_out, int out_size)
{
    (void)in_sizes; (void)n_in; (void)out_size;
    const float* x     = (const float*)d_in[0];
    const float* Wg0   = (const float*)d_in[1];
    const float* bg0   = (const float*)d_in[2];
    const float* Wg1   = (const float*)d_in[3];
    const float* bg1   = (const float*)d_in[4];
    const float* W_out = (const float*)d_in[5];
    const float* b_out = (const float*)d_in[6];

    cudaFuncSetAttribute(lstm_persist,
                         cudaFuncAttributeMaxDynamicSharedMemorySize, SMEM_BYTES);

    convert_x<<<dim3(SEQ, 256/32, BATCH/32), dim3(32, 8)>>>(x);
    lstm_persist<<<NBLK, NTHR, SMEM_BYTES>>>(Wg0, bg0, Wg1, bg1, W_out, b_out,
                                             (float*)d_out);
}